// round 1
// baseline (speedup 1.0000x reference)
#include <cuda_runtime.h>
#include <cuda_bf16.h>

// SparseBoundaryContent: x [16, 512, 64] f32.
// boundary(i,j) = (x[i]+x[j])/2 on masked cells, content(i,j) = max(x[i..j])
// on masked cells, 0 elsewhere. mask per closed form below.
// Output layout (flat f32): [boundary B*D*N*N][content B*D*N*N][mask B*N*N].

#define NB 16
#define ND 512
#define NN 64

__device__ __forceinline__ bool cell_mask(int i, int d) {
    // d = j - i
    if (d < 0) return false;
    if (d <= 15) return true;                           // stride-1 offsets 1..15 (+diag)
    if (d <= 31) return (d & 1) && !(i & 1);            // stride-2: odd offsets 17..31
    return (d >= 35) && ((d & 3) == 3) && !(i & 3);     // stride-4: offsets 35,39,...,63
}

__global__ void __launch_bounds__(256)
sbc_kernel(const float* __restrict__ x,
           float* __restrict__ boundary,
           float* __restrict__ content,
           float* __restrict__ mask_out)
{
    __shared__ float M[7][NN];   // sparse table: M[k][i] = max x[i .. i+2^k-1] (clamped)

    const int bd  = blockIdx.x;          // bd = b*ND + d
    const int tid = threadIdx.x;

    // Load this row of x into level 0.
    if (tid < NN) M[0][tid] = x[(size_t)bd * NN + tid];
    __syncthreads();

    // Build sparse max table (6 doubling steps).
    #pragma unroll
    for (int k = 1; k < 7; k++) {
        const int half = 1 << (k - 1);
        if (tid < NN) {
            int other = tid + half;
            if (other > NN - 1) other = NN - 1;
            M[k][tid] = fmaxf(M[k - 1][tid], M[k - 1][other]);
        }
        __syncthreads();
    }

    float* bptr = boundary + (size_t)bd * (NN * NN);
    float* cptr = content  + (size_t)bd * (NN * NN);

    // 4096 cells per map; 256 threads * 4 passes * float4.
    #pragma unroll
    for (int p = 0; p < 4; p++) {
        const int base = p * 1024 + tid * 4;   // cell index; 4 consecutive j, same i
        const int i  = base >> 6;
        const int j0 = base & 63;
        const float xi = M[0][i];

        float bo[4], co[4];
        #pragma unroll
        for (int e = 0; e < 4; e++) {
            const int j = j0 + e;
            const int d = j - i;
            float bv = 0.0f, cv = 0.0f;
            if (cell_mask(i, d)) {
                bv = (xi + M[0][j]) * 0.5f;
                const int len = d + 1;
                const int k = 31 - __clz(len);          // floor(log2(len))
                cv = fmaxf(M[k][i], M[k][j + 1 - (1 << k)]);
            }
            bo[e] = bv;
            co[e] = cv;
        }
        *reinterpret_cast<float4*>(bptr + base) = make_float4(bo[0], bo[1], bo[2], bo[3]);
        *reinterpret_cast<float4*>(cptr + base) = make_float4(co[0], co[1], co[2], co[3]);
    }

    // Blocks with d == 0 write the (broadcast) mask slice for their batch b.
    if ((bd % ND) == 0) {
        float* mptr = mask_out + (size_t)(bd / ND) * (NN * NN);
        #pragma unroll
        for (int p = 0; p < 4; p++) {
            const int base = p * 1024 + tid * 4;
            const int i  = base >> 6;
            const int j0 = base & 63;
            float mo[4];
            #pragma unroll
            for (int e = 0; e < 4; e++) {
                const int j = j0 + e;
                mo[e] = cell_mask(i, j - i) ? 1.0f : 0.0f;
            }
            *reinterpret_cast<float4*>(mptr + base) = make_float4(mo[0], mo[1], mo[2], mo[3]);
        }
    }
}

extern "C" void kernel_launch(void* const* d_in, const int* in_sizes, int n_in,
                              void* d_out, int out_size) {
    const float* x = (const float*)d_in[0];
    float* out = (float*)d_out;

    const size_t map_elems = (size_t)NB * ND * NN * NN;   // 33,554,432
    float* boundary = out;
    float* content  = out + map_elems;
    float* mask_out = out + 2 * map_elems;

    sbc_kernel<<<NB * ND, 256>>>(x, boundary, content, mask_out);
}

// round 3
// speedup vs baseline: 1.1712x; 1.1712x over previous
#include <cuda_runtime.h>
#include <cuda_bf16.h>

// SparseBoundaryContent: x [16, 512, 64] f32.
// boundary(i,j) = (x[i]+x[j])/2 on masked cells, content(i,j) = max(x[i..j])
// on masked cells, 0 elsewhere.
// Output layout (flat f32): [boundary B*D*N*N][content B*D*N*N][mask B*N*N].
//
// All pattern-dependent work (mask, RMQ level/offsets, masked-cell list) is
// computed at COMPILE TIME via constexpr and baked into a __device__ table.

#define NB 16
#define ND 512
#define NN 64
#define NCELLS 4096          // 64*64 cells per (b,d) row
#define NMASKED 1104         // masked cells per tile (incl. diagonal)

struct alignas(16) Tables {
    float        mask[NCELLS];     // 1.0 on masked cells, 0.0 elsewhere
    unsigned int meta[NMASKED];    // {cell:12} | {offL:9}<<12 | {offR:9}<<21
};

constexpr bool cell_mask_ct(int i, int j) {
    int d = j - i;
    if (d < 0)  return false;
    if (d <= 15) return true;                              // stride-1 offsets 0..15
    if (d <= 31) return (d & 1) && !(i & 1);               // stride-2: odd 17..31, i even
    return (d >= 35) && ((d & 3) == 3) && !(i & 3);        // stride-4: 35,39,..,63, i%4==0
}

constexpr int count_masked() {
    int c = 0;
    for (int i = 0; i < NN; i++)
        for (int j = 0; j < NN; j++)
            if (cell_mask_ct(i, j)) c++;
    return c;
}
static_assert(count_masked() == NMASKED, "masked cell count mismatch");

constexpr Tables gen_tables() {
    Tables t{};
    int cnt = 0;
    for (int i = 0; i < NN; i++) {
        for (int j = 0; j < NN; j++) {
            bool m = cell_mask_ct(i, j);
            t.mask[i * NN + j] = m ? 1.0f : 0.0f;
            if (m) {
                int len = j - i + 1;
                int k = 0;
                while ((1 << (k + 1)) <= len) k++;         // k = floor(log2(len))
                int ri = j + 1 - (1 << k);
                unsigned offL = (unsigned)(k * NN + i);    // flat index into Mf[7*64]
                unsigned offR = (unsigned)(k * NN + ri);
                t.meta[cnt++] = (unsigned)(i * NN + j) | (offL << 12) | (offR << 21);
            }
        }
    }
    return t;
}

__device__ constexpr Tables g_tab = gen_tables();

__global__ void __launch_bounds__(256)
sbc_kernel(const float* __restrict__ x,
           float* __restrict__ boundary,
           float* __restrict__ content,
           float* __restrict__ mask_out)
{
    __shared__ float Mf[7 * NN];       // sparse max table, Mf[0..63] = x row
    __shared__ float ctile[NCELLS];    // content values at masked cells, 0 elsewhere

    const int bd  = blockIdx.x;        // bd = b*ND + d
    const int tid = threadIdx.x;

    // Zero the content tile (16 KB) — guarantees exact zeros at unmasked cells.
    #pragma unroll
    for (int p = 0; p < 4; p++)
        *reinterpret_cast<float4*>(&ctile[(p * 256 + tid) * 4]) =
            make_float4(0.f, 0.f, 0.f, 0.f);

    if (tid < NN) Mf[tid] = x[(size_t)bd * NN + tid];
    __syncthreads();

    // Build sparse max table: Mf[k*64+i] = max x[i .. min(i+2^k-1, 63)]
    #pragma unroll
    for (int k = 1; k < 7; k++) {
        if (tid < NN) {
            int o = tid + (1 << (k - 1));
            if (o > NN - 1) o = NN - 1;
            Mf[k * NN + tid] = fmaxf(Mf[(k - 1) * NN + tid], Mf[(k - 1) * NN + o]);
        }
        __syncthreads();
    }

    // Phase 1: fill content at the 1104 masked cells (one RMQ each).
    #pragma unroll
    for (int p = 0; p < 5; p++) {
        int idx = p * 256 + tid;
        if (idx < NMASKED) {
            unsigned m = g_tab.meta[idx];
            ctile[m & 4095u] = fmaxf(Mf[(m >> 12) & 511u], Mf[(m >> 21) & 511u]);
        }
    }
    __syncthreads();

    float* bptr = boundary + (size_t)bd * NCELLS;
    float* cptr = content  + (size_t)bd * NCELLS;

    // Phase 2: stream out both maps, 4 cells per thread per pass.
    #pragma unroll
    for (int p = 0; p < 4; p++) {
        const int g  = p * 256 + tid;     // 4-cell group index
        const int c0 = g * 4;             // first cell of group
        const int i  = g >> 4;            // row
        const float xih = 0.5f * Mf[i];

        const float4 mk = *reinterpret_cast<const float4*>(&g_tab.mask[c0]);
        const float4 xj = *reinterpret_cast<const float4*>(&Mf[c0 & 63]);
        const float4 ct = *reinterpret_cast<const float4*>(&ctile[c0]);

        float4 bo, co;
        bo.x = fmaf(0.5f, xj.x, xih) * mk.x;
        bo.y = fmaf(0.5f, xj.y, xih) * mk.y;
        bo.z = fmaf(0.5f, xj.z, xih) * mk.z;
        bo.w = fmaf(0.5f, xj.w, xih) * mk.w;
        co.x = ct.x * mk.x;
        co.y = ct.y * mk.y;
        co.z = ct.z * mk.z;
        co.w = ct.w * mk.w;

        *reinterpret_cast<float4*>(bptr + c0) = bo;
        *reinterpret_cast<float4*>(cptr + c0) = co;
    }

    // The 16 CTAs with d == 0 also emit the broadcast mask slice for batch b.
    if ((bd & (ND - 1)) == 0) {
        float* mp = mask_out + (size_t)(bd >> 9) * NCELLS;
        #pragma unroll
        for (int p = 0; p < 4; p++) {
            const int c0 = (p * 256 + tid) * 4;
            *reinterpret_cast<float4*>(mp + c0) =
                *reinterpret_cast<const float4*>(&g_tab.mask[c0]);
        }
    }
}

extern "C" void kernel_launch(void* const* d_in, const int* in_sizes, int n_in,
                              void* d_out, int out_size) {
    const float* x = (const float*)d_in[0];
    float* out = (float*)d_out;

    const size_t map_elems = (size_t)NB * ND * NN * NN;   // 33,554,432
    float* boundary = out;
    float* content  = out + map_elems;
    float* mask_out = out + 2 * map_elems;

    sbc_kernel<<<NB * ND, 256>>>(x, boundary, content, mask_out);
}